// round 9
// baseline (speedup 1.0000x reference)
#include <cuda_runtime.h>
#include <cstdint>
#include <math.h>

#define DIMX   1536
#define QKVD   4608
#define NHEADS 24
#define HDIM   64
#define BB     2
#define NXX    2048
#define NCC    256
#define NTOTAL 2304
#define ATT_SCALE 0.125f
#define SSTR   68
#define GSTR   20

// Scratch [B,H,N,D]
__device__ float g_q[(size_t)BB*NHEADS*NTOTAL*HDIM];
__device__ float g_k[(size_t)BB*NHEADS*NTOTAL*HDIM];
__device__ float g_v[(size_t)BB*NHEADS*NTOTAL*HDIM];
__device__ float g_o[(size_t)BB*NHEADS*NTOTAL*HDIM];

__device__ __forceinline__ uint32_t f2tf(float x) {
    uint32_t u;
    asm("cvt.rna.tf32.f32 %0, %1;" : "=r"(u) : "f"(x));
    return u;
}
__device__ __forceinline__ uint32_t u2tf(uint32_t ubits) {
    uint32_t u;
    asm("cvt.rna.tf32.f32 %0, %1;" : "=r"(u) : "f"(__uint_as_float(ubits)));
    return u;
}
__device__ __forceinline__ void mma_tf32(float* d, const uint32_t* a, uint32_t b0, uint32_t b1) {
    asm volatile(
        "mma.sync.aligned.m16n8k8.row.col.f32.tf32.tf32.f32 "
        "{%0,%1,%2,%3}, {%4,%5,%6,%7}, {%8,%9}, {%0,%1,%2,%3};"
        : "+f"(d[0]), "+f"(d[1]), "+f"(d[2]), "+f"(d[3])
        : "r"(a[0]), "r"(a[1]), "r"(a[2]), "r"(a[3]), "r"(b0), "r"(b1));
}
__device__ __forceinline__ uint32_t s2u(const void* p) {
    return (uint32_t)__cvta_generic_to_shared(p);
}
__device__ __forceinline__ void cp16(uint32_t dst, const void* src) {
    asm volatile("cp.async.cg.shared.global [%0], [%1], 16;" :: "r"(dst), "l"(src));
}
#define CP_COMMIT() asm volatile("cp.async.commit_group;" ::: "memory")
#define CP_WAIT0()  asm volatile("cp.async.wait_group 0;" ::: "memory")
#define CP_WAIT1()  asm volatile("cp.async.wait_group 1;" ::: "memory")

// ===========================================================================
// GEMM compute core, k-permuted smem layout:
//   storage col s = ks*8 + qt*2 + kh   (k = ks*8 + kh*4 + qt)
// so fragment pairs (k=qt, k=qt+4) are adjacent -> LDS.64
// ===========================================================================
__device__ __forceinline__ void gemm_tile_compute(
    const uint32_t* __restrict__ As, const uint32_t* __restrict__ Bs,
    int mbase, int nbase, int qg, int qt2, float acc[2][8][4])
{
#pragma unroll
    for (int kf = 0; kf < 2; kf++) {
        int kc = kf * 8;
        uint32_t a[2][4], b[8][2];
#pragma unroll
        for (int mf = 0; mf < 2; mf++) {
            int r = mbase + mf * 16;
            uint2 p0 = *(const uint2*)&As[(r + qg) * GSTR + kc + qt2];
            uint2 p1 = *(const uint2*)&As[(r + qg + 8) * GSTR + kc + qt2];
            a[mf][0] = p0.x; a[mf][1] = p1.x; a[mf][2] = p0.y; a[mf][3] = p1.y;
        }
#pragma unroll
        for (int nf = 0; nf < 8; nf++) {
            uint2 pb = *(const uint2*)&Bs[(nbase + nf * 8 + qg) * GSTR + kc + qt2];
            b[nf][0] = pb.x; b[nf][1] = pb.y;
        }
#pragma unroll
        for (int mf = 0; mf < 2; mf++)
#pragma unroll
            for (int nf = 0; nf < 8; nf++)
                mma_tf32(acc[mf][nf], a[mf], b[nf][0], b[nf][1]);
    }
}

// permuted scalar store of one float4 (4 consecutive k, same row)
__device__ __forceinline__ void sts_perm(uint32_t* base, int r, int f4, float4 v) {
    // f4 in 0..3 selects k block of 4: ks = f4>>1, kh = f4&1
    uint32_t* d = base + r * GSTR + (f4 >> 1) * 8 + (f4 & 1);
    d[0] = f2tf(v.x); d[2] = f2tf(v.y); d[4] = f2tf(v.z); d[6] = f2tf(v.w);
}

// ---------------------------------------------------------------------------
// QKV GEMM, double-buffered smem with register-staged prefetch
// ---------------------------------------------------------------------------
__global__ __launch_bounds__(256) void qkv_mma_kernel(
    const float* __restrict__ A, const float* __restrict__ W,
    const float* __restrict__ bias, int Nt, int n_off)
{
    __shared__ uint32_t As[2][128 * GSTR];
    __shared__ uint32_t Bs[2][128 * GSTR];
    const int tid = threadIdx.x;
    const int w = tid >> 5, lane = tid & 31;
    const int qg = lane >> 2, qt = lane & 3;
    const int qt2 = qt * 2;
    const int mbase = (w & 3) * 32, nbase = (w >> 2) * 64;
    const int rowBase = blockIdx.y * 128;
    const int colBase = blockIdx.x * 128;

    int lr[2], lf[2];
#pragma unroll
    for (int i = 0; i < 2; i++) {
        int lin = tid + i * 256;
        lr[i] = lin >> 2; lf[i] = lin & 3;
    }

    float acc[2][8][4];
#pragma unroll
    for (int mf = 0; mf < 2; mf++)
#pragma unroll
        for (int nf = 0; nf < 8; nf++)
#pragma unroll
            for (int e = 0; e < 4; e++) acc[mf][nf][e] = 0.f;

    float4 pa[2], pw[2];
#pragma unroll
    for (int i = 0; i < 2; i++) {
        pa[i] = *(const float4*)(A + (size_t)(rowBase + lr[i]) * DIMX + lf[i] * 4);
        pw[i] = *(const float4*)(W + (size_t)(colBase + lr[i]) * DIMX + lf[i] * 4);
    }
#pragma unroll
    for (int i = 0; i < 2; i++) {
        sts_perm(As[0], lr[i], lf[i], pa[i]);
        sts_perm(Bs[0], lr[i], lf[i], pw[i]);
    }
    __syncthreads();

    int buf = 0;
    for (int k0 = 0; k0 < DIMX; k0 += 16) {
        const int kn = k0 + 16;
        const bool has = kn < DIMX;
        if (has) {
#pragma unroll
            for (int i = 0; i < 2; i++) {
                pa[i] = *(const float4*)(A + (size_t)(rowBase + lr[i]) * DIMX + kn + lf[i] * 4);
                pw[i] = *(const float4*)(W + (size_t)(colBase + lr[i]) * DIMX + kn + lf[i] * 4);
            }
        }
        gemm_tile_compute(As[buf], Bs[buf], mbase, nbase, qg, qt2, acc);
        if (has) {
#pragma unroll
            for (int i = 0; i < 2; i++) {
                sts_perm(As[buf ^ 1], lr[i], lf[i], pa[i]);
                sts_perm(Bs[buf ^ 1], lr[i], lf[i], pw[i]);
            }
            __syncthreads();
        }
        buf ^= 1;
    }

#pragma unroll
    for (int mf = 0; mf < 2; mf++) {
#pragma unroll
        for (int er = 0; er < 2; er++) {
            int r = rowBase + mbase + mf * 16 + qg + er * 8;
            int bi = r / Nt;
            int n = r - bi * Nt;
#pragma unroll
            for (int nf = 0; nf < 8; nf++) {
                int cidx = colBase + nbase + nf * 8 + 2 * qt;
                float v0 = acc[mf][nf][er * 2 + 0] + bias[cidx];
                float v1 = acc[mf][nf][er * 2 + 1] + bias[cidx + 1];
                int three = cidx / DIMX;
                int rem = cidx - three * DIMX;
                int h = rem >> 6, d = rem & 63;
                float* dst = (three == 0) ? g_q : (three == 1) ? g_k : g_v;
                *(float2*)(dst + (((size_t)bi * NHEADS + h) * NTOTAL + (n_off + n)) * HDIM + d)
                    = make_float2(v0, v1);
            }
        }
    }
}

// ---------------------------------------------------------------------------
// Flash attention, Br=128, 8 warps, cp.async double-buffered K/V, 2 CTAs/SM
// ---------------------------------------------------------------------------
#define ATT_KV_U32 (64 * SSTR)
#define ATT_Q_U32  (128 * SSTR)
#define ATT_SMEM_BYTES ((ATT_Q_U32 + 4 * ATT_KV_U32) * 4)

__global__ __launch_bounds__(256, 2) void attn_mma_kernel()
{
    extern __shared__ uint32_t sm[];
    uint32_t* Qs = sm;                                   // 128*SSTR, becomes Ps
    uint32_t* Kb[2] = { sm + ATT_Q_U32, sm + ATT_Q_U32 + ATT_KV_U32 };
    uint32_t* Vb[2] = { sm + ATT_Q_U32 + 2 * ATT_KV_U32, sm + ATT_Q_U32 + 3 * ATT_KV_U32 };

    const int tid = threadIdx.x;
    const int w = tid >> 5, lane = tid & 31;
    const int qg = lane >> 2, qt = lane & 3;
    const int h = blockIdx.y, bi = blockIdx.z;
    const size_t headbase = ((size_t)bi * NHEADS + h) * NTOTAL;
    const int qbase = blockIdx.x * 128;
    const int mrow = w * 16;

    auto issue_tile = [&](int jt, int b) {
        uint32_t kdst = s2u(Kb[b]);
        uint32_t vdst = s2u(Vb[b]);
#pragma unroll
        for (int i = 0; i < 4; i++) {
            int lin = tid + i * 256;
            int r = lin >> 4, c4 = (lin & 15) << 2;
            uint32_t off = (uint32_t)(r * SSTR + c4) * 4u;
            cp16(kdst + off, g_k + (headbase + jt + r) * HDIM + c4);
            cp16(vdst + off, g_v + (headbase + jt + r) * HDIM + c4);
        }
        CP_COMMIT();
    };

    issue_tile(0, 0);

#pragma unroll
    for (int i = 0; i < 8; i++) {
        int lin = tid + i * 256;
        int r = lin >> 4, c4 = (lin & 15) << 2;
        float4 t = *(const float4*)(g_q + (headbase + qbase + r) * HDIM + c4);
        uint32_t* d = &Qs[r * SSTR + c4];
        d[0] = f2tf(t.x); d[1] = f2tf(t.y); d[2] = f2tf(t.z); d[3] = f2tf(t.w);
    }
    __syncthreads();

    uint32_t qf[8][4];
#pragma unroll
    for (int kf = 0; kf < 8; kf++) {
        int kc = kf * 8;
        qf[kf][0] = Qs[(mrow + qg) * SSTR + kc + qt];
        qf[kf][1] = Qs[(mrow + qg + 8) * SSTR + kc + qt];
        qf[kf][2] = Qs[(mrow + qg) * SSTR + kc + qt + 4];
        qf[kf][3] = Qs[(mrow + qg + 8) * SSTR + kc + qt + 4];
    }
    __syncthreads();
    uint32_t* Ps = Qs;

    float of[8][4];
#pragma unroll
    for (int nf = 0; nf < 8; nf++)
#pragma unroll
        for (int e = 0; e < 4; e++) of[nf][e] = 0.f;
    float m0 = -1e30f, m1 = -1e30f, l0 = 0.f, l1 = 0.f;

    int buf = 0;
    for (int jt = 0; jt < NTOTAL; jt += 64) {
        const bool has = (jt + 64) < NTOTAL;
        if (has) issue_tile(jt + 64, buf ^ 1);
        if (has) { CP_WAIT1(); } else { CP_WAIT0(); }
        __syncthreads();

        const uint32_t* Kc = Kb[buf];
        const uint32_t* Vc = Vb[buf];

        float sf[8][4];
#pragma unroll
        for (int nf = 0; nf < 8; nf++)
#pragma unroll
            for (int e = 0; e < 4; e++) sf[nf][e] = 0.f;
#pragma unroll
        for (int kf = 0; kf < 8; kf++) {
            int kc = kf * 8;
#pragma unroll
            for (int nf = 0; nf < 8; nf++) {
                uint32_t b0 = u2tf(Kc[(nf * 8 + qg) * SSTR + kc + qt]);
                uint32_t b1 = u2tf(Kc[(nf * 8 + qg) * SSTR + kc + qt + 4]);
                mma_tf32(sf[nf], qf[kf], b0, b1);
            }
        }

        float mx0 = -1e30f, mx1 = -1e30f;
#pragma unroll
        for (int nf = 0; nf < 8; nf++) {
            sf[nf][0] *= ATT_SCALE; sf[nf][1] *= ATT_SCALE;
            sf[nf][2] *= ATT_SCALE; sf[nf][3] *= ATT_SCALE;
            mx0 = fmaxf(mx0, fmaxf(sf[nf][0], sf[nf][1]));
            mx1 = fmaxf(mx1, fmaxf(sf[nf][2], sf[nf][3]));
        }
        mx0 = fmaxf(mx0, __shfl_xor_sync(0xffffffffu, mx0, 1));
        mx0 = fmaxf(mx0, __shfl_xor_sync(0xffffffffu, mx0, 2));
        mx1 = fmaxf(mx1, __shfl_xor_sync(0xffffffffu, mx1, 1));
        mx1 = fmaxf(mx1, __shfl_xor_sync(0xffffffffu, mx1, 2));

        float nm0 = fmaxf(m0, mx0), nm1 = fmaxf(m1, mx1);
        float corr0 = __expf(m0 - nm0), corr1 = __expf(m1 - nm1);
        float s0 = 0.f, s1 = 0.f;
#pragma unroll
        for (int nf = 0; nf < 8; nf++) {
            float p00 = __expf(sf[nf][0] - nm0);
            float p01 = __expf(sf[nf][1] - nm0);
            float p10 = __expf(sf[nf][2] - nm1);
            float p11 = __expf(sf[nf][3] - nm1);
            s0 += p00 + p01; s1 += p10 + p11;
            int col = nf * 8 + 2 * qt;
            Ps[(mrow + qg) * SSTR + col]     = f2tf(p00);
            Ps[(mrow + qg) * SSTR + col + 1] = f2tf(p01);
            Ps[(mrow + qg + 8) * SSTR + col]     = f2tf(p10);
            Ps[(mrow + qg + 8) * SSTR + col + 1] = f2tf(p11);
            of[nf][0] *= corr0; of[nf][1] *= corr0;
            of[nf][2] *= corr1; of[nf][3] *= corr1;
        }
        s0 += __shfl_xor_sync(0xffffffffu, s0, 1);
        s0 += __shfl_xor_sync(0xffffffffu, s0, 2);
        s1 += __shfl_xor_sync(0xffffffffu, s1, 1);
        s1 += __shfl_xor_sync(0xffffffffu, s1, 2);
        l0 = l0 * corr0 + s0; l1 = l1 * corr1 + s1;
        m0 = nm0; m1 = nm1;
        __syncwarp();

#pragma unroll
        for (int kf = 0; kf < 8; kf++) {
            int jc = kf * 8;
            uint32_t a[4];
            a[0] = Ps[(mrow + qg) * SSTR + jc + qt];
            a[1] = Ps[(mrow + qg + 8) * SSTR + jc + qt];
            a[2] = Ps[(mrow + qg) * SSTR + jc + qt + 4];
            a[3] = Ps[(mrow + qg + 8) * SSTR + jc + qt + 4];
#pragma unroll
            for (int nf = 0; nf < 8; nf++) {
                uint32_t b0 = u2tf(Vc[(jc + qt) * SSTR + nf * 8 + qg]);
                uint32_t b1 = u2tf(Vc[(jc + qt + 4) * SSTR + nf * 8 + qg]);
                mma_tf32(of[nf], a, b0, b1);
            }
        }
        __syncthreads();
        buf ^= 1;
    }

    const float inv0 = 1.f / l0, inv1 = 1.f / l1;
    const int row0 = qbase + mrow + qg, row1 = row0 + 8;
#pragma unroll
    for (int nf = 0; nf < 8; nf++) {
        int col = nf * 8 + 2 * qt;
        *(float2*)(g_o + (headbase + row0) * HDIM + col)
            = make_float2(of[nf][0] * inv0, of[nf][1] * inv0);
        *(float2*)(g_o + (headbase + row1) * HDIM + col)
            = make_float2(of[nf][2] * inv1, of[nf][3] * inv1);
    }
}

// ---------------------------------------------------------------------------
// Projection GEMM, double-buffered, A gathered from g_o [B,H,N,D]
// ---------------------------------------------------------------------------
__global__ __launch_bounds__(256) void proj_mma_kernel(
    const float* __restrict__ W, const float* __restrict__ bias,
    float* __restrict__ out, int Nt, int n_off)
{
    __shared__ uint32_t As[2][128 * GSTR];
    __shared__ uint32_t Bs[2][128 * GSTR];
    const int tid = threadIdx.x;
    const int w = tid >> 5, lane = tid & 31;
    const int qg = lane >> 2, qt = lane & 3;
    const int qt2 = qt * 2;
    const int mbase = (w & 3) * 32, nbase = (w >> 2) * 64;
    const int rowBase = blockIdx.y * 128;
    const int colBase = blockIdx.x * 128;

    int lr[2], lf[2];
    size_t abase[2];
#pragma unroll
    for (int i = 0; i < 2; i++) {
        int lin = tid + i * 256;
        lr[i] = lin >> 2; lf[i] = lin & 3;
        int row = rowBase + lr[i];
        int bi = row / Nt;
        int n = row - bi * Nt;
        abase[i] = ((size_t)bi * NHEADS * NTOTAL + (n_off + n)) * HDIM;
    }

    float acc[2][8][4];
#pragma unroll
    for (int mf = 0; mf < 2; mf++)
#pragma unroll
        for (int nf = 0; nf < 8; nf++)
#pragma unroll
            for (int e = 0; e < 4; e++) acc[mf][nf][e] = 0.f;

    auto fetch = [&](int k0, float4* pa, float4* pw) {
#pragma unroll
        for (int i = 0; i < 2; i++) {
            int k = k0 + lf[i] * 4;
            int hh = k >> 6, dd = k & 63;
            pa[i] = *(const float4*)(g_o + abase[i] + (size_t)hh * NTOTAL * HDIM + dd);
            pw[i] = *(const float4*)(W + (size_t)(colBase + lr[i]) * DIMX + k);
        }
    };
    auto store = [&](int b, const float4* pa, const float4* pw) {
#pragma unroll
        for (int i = 0; i < 2; i++) {
            sts_perm(As[b], lr[i], lf[i], pa[i]);
            sts_perm(Bs[b], lr[i], lf[i], pw[i]);
        }
    };

    float4 pa[2], pw[2];
    fetch(0, pa, pw);
    store(0, pa, pw);
    __syncthreads();

    int buf = 0;
    for (int k0 = 0; k0 < DIMX; k0 += 16) {
        const int kn = k0 + 16;
        const bool has = kn < DIMX;
        if (has) fetch(kn, pa, pw);
        gemm_tile_compute(As[buf], Bs[buf], mbase, nbase, qg, qt2, acc);
        if (has) {
            store(buf ^ 1, pa, pw);
            __syncthreads();
        }
        buf ^= 1;
    }

#pragma unroll
    for (int mf = 0; mf < 2; mf++) {
#pragma unroll
        for (int er = 0; er < 2; er++) {
            int r = rowBase + mbase + mf * 16 + qg + er * 8;
#pragma unroll
            for (int nf = 0; nf < 8; nf++) {
                int cidx = colBase + nbase + nf * 8 + 2 * qt;
                float v0 = acc[mf][nf][er * 2 + 0] + bias[cidx];
                float v1 = acc[mf][nf][er * 2 + 1] + bias[cidx + 1];
                *(float2*)(out + (size_t)r * DIMX + cidx) = make_float2(v0, v1);
            }
        }
    }
}

// ---------------------------------------------------------------------------
extern "C" void kernel_launch(void* const* d_in, const int* in_sizes, int n_in,
                              void* d_out, int out_size)
{
    const float* x       = (const float*)d_in[0];
    const float* c       = (const float*)d_in[1];
    const float* Wqkv_x  = (const float*)d_in[2];
    const float* bqkv_x  = (const float*)d_in[3];
    const float* Wqkv_c  = (const float*)d_in[4];
    const float* bqkv_c  = (const float*)d_in[5];
    const float* Wproj_x = (const float*)d_in[6];
    const float* bproj_x = (const float*)d_in[7];
    const float* Wproj_c = (const float*)d_in[8];
    const float* bproj_c = (const float*)d_in[9];
    float* out = (float*)d_out;

    cudaFuncSetAttribute(attn_mma_kernel,
                         cudaFuncAttributeMaxDynamicSharedMemorySize, ATT_SMEM_BYTES);

    qkv_mma_kernel<<<dim3(QKVD / 128, (BB * NXX) / 128), 256>>>(x, Wqkv_x, bqkv_x, NXX, 0);
    qkv_mma_kernel<<<dim3(QKVD / 128, (BB * NCC) / 128), 256>>>(c, Wqkv_c, bqkv_c, NCC, NXX);

    attn_mma_kernel<<<dim3(NTOTAL / 128, NHEADS, BB), 256, ATT_SMEM_BYTES>>>();

    proj_mma_kernel<<<dim3(DIMX / 128, (BB * NXX) / 128), 256>>>(
        Wproj_x, bproj_x, out, NXX, 0);
    proj_mma_kernel<<<dim3(DIMX / 128, (BB * NCC) / 128), 256>>>(
        Wproj_c, bproj_c, out + (size_t)BB * NXX * DIMX, NCC, NXX);
}

// round 11
// speedup vs baseline: 2.6316x; 2.6316x over previous
#include <cuda_runtime.h>
#include <cuda_fp16.h>
#include <cstdint>
#include <math.h>

#define DIMX   1536
#define QKVD   4608
#define NHEADS 24
#define HDIM   64
#define BB     2
#define NXX    2048
#define NCC    256
#define NTOTAL 2304
#define ATT_SCALE 0.125f

// ---------------- fp16 scratch (device globals; no allocation) -------------
__device__ __half g_hx[(size_t)BB*NXX*DIMX];
__device__ __half g_hc[(size_t)BB*NCC*DIMX];
__device__ __half g_hWqx[(size_t)QKVD*DIMX];
__device__ __half g_hWqc[(size_t)QKVD*DIMX];
__device__ __half g_hWpx[(size_t)DIMX*DIMX];
__device__ __half g_hWpc[(size_t)DIMX*DIMX];
// q/k/v/o scratch [B,H,N,D] fp16
__device__ __half g_q[(size_t)BB*NHEADS*NTOTAL*HDIM];
__device__ __half g_k[(size_t)BB*NHEADS*NTOTAL*HDIM];
__device__ __half g_v[(size_t)BB*NHEADS*NTOTAL*HDIM];
__device__ __half g_o[(size_t)BB*NHEADS*NTOTAL*HDIM];

// ---------------- helpers ----------------
__device__ __forceinline__ uint32_t s2u(const void* p) {
    return (uint32_t)__cvta_generic_to_shared(p);
}
__device__ __forceinline__ void cp16(uint32_t dst, const void* src) {
    asm volatile("cp.async.cg.shared.global [%0], [%1], 16;" :: "r"(dst), "l"(src));
}
#define CP_COMMIT() asm volatile("cp.async.commit_group;" ::: "memory")
#define CP_WAIT0()  asm volatile("cp.async.wait_group 0;" ::: "memory")
#define CP_WAIT1()  asm volatile("cp.async.wait_group 1;" ::: "memory")

__device__ __forceinline__ void ldsm4(uint32_t& r0, uint32_t& r1, uint32_t& r2,
                                      uint32_t& r3, uint32_t addr) {
    asm volatile("ldmatrix.sync.aligned.m8n8.x4.shared.b16 {%0,%1,%2,%3}, [%4];"
                 : "=r"(r0), "=r"(r1), "=r"(r2), "=r"(r3) : "r"(addr));
}
__device__ __forceinline__ void ldsm4t(uint32_t& r0, uint32_t& r1, uint32_t& r2,
                                       uint32_t& r3, uint32_t addr) {
    asm volatile("ldmatrix.sync.aligned.m8n8.x4.trans.shared.b16 {%0,%1,%2,%3}, [%4];"
                 : "=r"(r0), "=r"(r1), "=r"(r2), "=r"(r3) : "r"(addr));
}
__device__ __forceinline__ void mma_f16(float* d, const uint32_t* a,
                                        uint32_t b0, uint32_t b1) {
    asm volatile(
        "mma.sync.aligned.m16n8k16.row.col.f32.f16.f16.f32 "
        "{%0,%1,%2,%3}, {%4,%5,%6,%7}, {%8,%9}, {%0,%1,%2,%3};"
        : "+f"(d[0]), "+f"(d[1]), "+f"(d[2]), "+f"(d[3])
        : "r"(a[0]), "r"(a[1]), "r"(a[2]), "r"(a[3]), "r"(b0), "r"(b1));
}

// ---------------- fp32 -> fp16 conversion kernel ----------------
__global__ __launch_bounds__(256) void f2h_kernel(
    const float* __restrict__ s, __half* __restrict__ d, int n)
{
    int i = (blockIdx.x * 256 + threadIdx.x) * 4;
    if (i >= n) return;
    float4 v = *(const float4*)(s + i);
    __half2* dp = (__half2*)(d + i);
    dp[0] = __floats2half2_rn(v.x, v.y);
    dp[1] = __floats2half2_rn(v.z, v.w);
}

// ======================= fp16 tensor-core GEMM =======================
// C[128,128 tile] = A[M,1536] @ W[N,1536]^T (+bias).
// K-tile 32 halves, 3-stage cp.async, fragments via ldmatrix.
// MODE 0: A fp16 row-major, epilogue scatters half2 into g_q/g_k/g_v
// MODE 1: A gathered from g_o [B,H,N,D] fp16, epilogue fp32 +bias to out
#define GK      32
#define GROWB   80                    // bytes per padded row (40 halves)
#define GOP_BYTES (128 * GROWB)       // 10240
#define GSTAGE  (2 * GOP_BYTES)       // 20480
#define GEMM_SMEM (3 * GSTAGE)        // 61440
#define GNITER  (DIMX / GK)           // 48

template<int MODE>
__global__ __launch_bounds__(256, 2) void gemm_h_kernel(
    const __half* __restrict__ A, const __half* __restrict__ Wt,
    const float* __restrict__ bias, float* __restrict__ outf,
    int Nt, int n_off)
{
    extern __shared__ char dsm[];
    const uint32_t smem0 = s2u(dsm);
    const int tid = threadIdx.x;
    const int w = tid >> 5, lane = tid & 31;
    const int qg = lane >> 2, qt = lane & 3;
    const int mi = lane >> 3, ri = lane & 7;
    const int mbase = (w & 3) * 32, nbase = (w >> 2) * 64;
    const int rowBase = blockIdx.y * 128;
    const int colBase = blockIdx.x * 128;

    // loader slots: 2 per thread, each one 16B chunk of A and of B
    const __half* asrc[2];
    const __half* wsrc[2];
    uint32_t dsto[2];
    int chh[2];
#pragma unroll
    for (int j = 0; j < 2; j++) {
        int slot = tid + j * 256;          // 0..511
        int r = slot >> 2, ch = slot & 3;  // row, 16B-chunk
        dsto[j] = (uint32_t)(r * GROWB + ch * 16);
        chh[j] = ch;
        wsrc[j] = Wt + (size_t)(colBase + r) * DIMX;
        if (MODE == 0) {
            asrc[j] = A + (size_t)(rowBase + r) * DIMX;
        } else {
            int row = rowBase + r;
            int bi = row / Nt;
            int n = row - bi * Nt;
            asrc[j] = g_o + ((size_t)bi * NHEADS * NTOTAL + n_off + n) * HDIM;
        }
    }

    auto issue = [&](int it) {
        const int k0 = it * GK;
        const uint32_t sa = smem0 + (it % 3) * GSTAGE;
        const uint32_t sb = sa + GOP_BYTES;
#pragma unroll
        for (int j = 0; j < 2; j++) {
            const __half* s;
            if (MODE == 0) {
                s = asrc[j] + k0 + chh[j] * 8;
            } else {
                int h = k0 >> 6;
                int d = (k0 & 63) + chh[j] * 8;
                s = asrc[j] + (size_t)h * (NTOTAL * HDIM) + d;
            }
            cp16(sa + dsto[j], s);
            cp16(sb + dsto[j], wsrc[j] + k0 + chh[j] * 8);
        }
        CP_COMMIT();
    };

    float acc[2][8][4];
#pragma unroll
    for (int mf = 0; mf < 2; mf++)
#pragma unroll
        for (int nf = 0; nf < 8; nf++)
#pragma unroll
            for (int e = 0; e < 4; e++) acc[mf][nf][e] = 0.f;

    issue(0);
    issue(1);
    for (int it = 0; it < GNITER; it++) {
        if (it < GNITER - 1) { CP_WAIT1(); } else { CP_WAIT0(); }
        __syncthreads();
        if (it + 2 < GNITER) issue(it + 2);
        const uint32_t sa = smem0 + (it % 3) * GSTAGE;
        const uint32_t sb = sa + GOP_BYTES;
#pragma unroll
        for (int kc = 0; kc < 2; kc++) {
            const int kcb = kc * 32;    // byte offset of 16-half k-slice
            uint32_t a[2][4], b[8][2];
#pragma unroll
            for (int mf = 0; mf < 2; mf++) {
                uint32_t ad = sa + (uint32_t)((mbase + mf * 16 + (mi & 1) * 8 + ri) * GROWB
                                              + kcb + (mi >> 1) * 16);
                ldsm4(a[mf][0], a[mf][1], a[mf][2], a[mf][3], ad);
            }
#pragma unroll
            for (int np = 0; np < 4; np++) {
                uint32_t bd = sb + (uint32_t)((nbase + np * 16 + (mi >> 1) * 8 + ri) * GROWB
                                              + kcb + (mi & 1) * 16);
                uint32_t r0, r1, r2, r3;
                ldsm4(r0, r1, r2, r3, bd);
                b[2 * np][0] = r0; b[2 * np][1] = r1;
                b[2 * np + 1][0] = r2; b[2 * np + 1][1] = r3;
            }
#pragma unroll
            for (int mf = 0; mf < 2; mf++)
#pragma unroll
                for (int nf = 0; nf < 8; nf++)
                    mma_f16(acc[mf][nf], a[mf], b[nf][0], b[nf][1]);
        }
    }

    // epilogue
#pragma unroll
    for (int mf = 0; mf < 2; mf++) {
#pragma unroll
        for (int er = 0; er < 2; er++) {
            int r = rowBase + mbase + mf * 16 + qg + er * 8;
            if (MODE == 0) {
                int bi = r / Nt;
                int n = r - bi * Nt;
#pragma unroll
                for (int nf = 0; nf < 8; nf++) {
                    int cidx = colBase + nbase + nf * 8 + 2 * qt;
                    float v0 = acc[mf][nf][er * 2 + 0] + bias[cidx];
                    float v1 = acc[mf][nf][er * 2 + 1] + bias[cidx + 1];
                    int three = cidx / DIMX;
                    int rem = cidx - three * DIMX;
                    int h = rem >> 6, d = rem & 63;
                    __half* dst = (three == 0) ? g_q : (three == 1) ? g_k : g_v;
                    *(__half2*)(dst + (((size_t)bi * NHEADS + h) * NTOTAL + (n_off + n)) * HDIM + d)
                        = __floats2half2_rn(v0, v1);
                }
            } else {
#pragma unroll
                for (int nf = 0; nf < 8; nf++) {
                    int cidx = colBase + nbase + nf * 8 + 2 * qt;
                    float v0 = acc[mf][nf][er * 2 + 0] + bias[cidx];
                    float v1 = acc[mf][nf][er * 2 + 1] + bias[cidx + 1];
                    *(float2*)(outf + (size_t)r * DIMX + cidx) = make_float2(v0, v1);
                }
            }
        }
    }
}

// ======================= fp16 flash attention =======================
// Br=128 (8 warps x 16 rows), Bc=64, fp16 K/V via cp.async double buffer,
// fragments via ldmatrix (V via ldmatrix.trans). P reuses Q smem.
#define AROWB 144                     // bytes per padded 64-half row (72 halves)
#define AQ_BYTES  (128 * AROWB)       // 18432
#define AKV_BYTES (64 * AROWB)        // 9216
#define ATT_SMEM (AQ_BYTES + 4 * AKV_BYTES)   // 55296

__global__ __launch_bounds__(256, 2) void attn_h_kernel()
{
    extern __shared__ char dsm[];
    const uint32_t Qb = s2u(dsm);
    uint32_t Kb[2] = { Qb + AQ_BYTES, Qb + AQ_BYTES + AKV_BYTES };
    uint32_t Vb[2] = { Qb + AQ_BYTES + 2 * AKV_BYTES, Qb + AQ_BYTES + 3 * AKV_BYTES };

    const int tid = threadIdx.x;
    const int w = tid >> 5, lane = tid & 31;
    const int qg = lane >> 2, qt = lane & 3;
    const int mi = lane >> 3, ri = lane & 7;
    const int h = blockIdx.y, bi = blockIdx.z;
    const size_t headbase = ((size_t)bi * NHEADS + h) * NTOTAL;
    const int qbase = blockIdx.x * 128;
    const int mrow = w * 16;

    auto issue_tile = [&](int jt, int b) {
#pragma unroll
        for (int i = 0; i < 2; i++) {
            int slot = tid + i * 256;          // 0..511
            int r = slot >> 3, ch = slot & 7;  // row, 16B chunk (8 halves)
            uint32_t off = (uint32_t)(r * AROWB + ch * 16);
            cp16(Kb[b] + off, g_k + (headbase + jt + r) * HDIM + ch * 8);
            cp16(Vb[b] + off, g_v + (headbase + jt + r) * HDIM + ch * 8);
        }
        CP_COMMIT();
    };

    issue_tile(0, 0);

    // stage Q (fp16 direct copy) — FULL rows: 128 rows x 8 chunks (1024 slots)
    {
        __half* Qp = (__half*)dsm;
#pragma unroll
        for (int i = 0; i < 4; i++) {
            int slot = tid + i * 256;           // 0..1023
            int r = slot >> 3, ch = slot & 7;   // row 0..127, chunk 0..7
            uint4 t = *(const uint4*)(g_q + (headbase + qbase + r) * HDIM + ch * 8);
            *(uint4*)(Qp + r * 72 + ch * 8) = t;
        }
    }
    __syncthreads();

    // extract Q fragments: 4 d-slices of 16
    uint32_t qf[4][4];
#pragma unroll
    for (int kf = 0; kf < 4; kf++) {
        uint32_t ad = Qb + (uint32_t)((mrow + (mi & 1) * 8 + ri) * AROWB
                                      + kf * 32 + (mi >> 1) * 16);
        ldsm4(qf[kf][0], qf[kf][1], qf[kf][2], qf[kf][3], ad);
    }
    __syncthreads();
    const uint32_t Pb = Qb;           // P overwrites Q staging
    __half* Pp = (__half*)dsm;

    float of[8][4];
#pragma unroll
    for (int nf = 0; nf < 8; nf++)
#pragma unroll
        for (int e = 0; e < 4; e++) of[nf][e] = 0.f;
    float m0 = -1e30f, m1 = -1e30f, l0 = 0.f, l1 = 0.f;

    int buf = 0;
    for (int jt = 0; jt < NTOTAL; jt += 64) {
        const bool has = (jt + 64) < NTOTAL;
        if (has) issue_tile(jt + 64, buf ^ 1);
        if (has) { CP_WAIT1(); } else { CP_WAIT0(); }
        __syncthreads();

        const uint32_t Kc = Kb[buf];
        const uint32_t Vc = Vb[buf];

        // S = Q K^T : 4 kf x 8 nf
        float sf[8][4];
#pragma unroll
        for (int nf = 0; nf < 8; nf++)
#pragma unroll
            for (int e = 0; e < 4; e++) sf[nf][e] = 0.f;
#pragma unroll
        for (int kf = 0; kf < 4; kf++) {
            const int dcb = kf * 32;
#pragma unroll
            for (int np = 0; np < 4; np++) {
                uint32_t kd = Kc + (uint32_t)((np * 16 + (mi >> 1) * 8 + ri) * AROWB
                                              + dcb + (mi & 1) * 16);
                uint32_t r0, r1, r2, r3;
                ldsm4(r0, r1, r2, r3, kd);
                mma_f16(sf[2 * np], qf[kf], r0, r1);
                mma_f16(sf[2 * np + 1], qf[kf], r2, r3);
            }
        }

        // online softmax (rows warp-private; quad reduce)
        float mx0 = -1e30f, mx1 = -1e30f;
#pragma unroll
        for (int nf = 0; nf < 8; nf++) {
            sf[nf][0] *= ATT_SCALE; sf[nf][1] *= ATT_SCALE;
            sf[nf][2] *= ATT_SCALE; sf[nf][3] *= ATT_SCALE;
            mx0 = fmaxf(mx0, fmaxf(sf[nf][0], sf[nf][1]));
            mx1 = fmaxf(mx1, fmaxf(sf[nf][2], sf[nf][3]));
        }
        mx0 = fmaxf(mx0, __shfl_xor_sync(0xffffffffu, mx0, 1));
        mx0 = fmaxf(mx0, __shfl_xor_sync(0xffffffffu, mx0, 2));
        mx1 = fmaxf(mx1, __shfl_xor_sync(0xffffffffu, mx1, 1));
        mx1 = fmaxf(mx1, __shfl_xor_sync(0xffffffffu, mx1, 2));

        float nm0 = fmaxf(m0, mx0), nm1 = fmaxf(m1, mx1);
        float corr0 = __expf(m0 - nm0), corr1 = __expf(m1 - nm1);
        float s0 = 0.f, s1 = 0.f;
#pragma unroll
        for (int nf = 0; nf < 8; nf++) {
            float p00 = __expf(sf[nf][0] - nm0);
            float p01 = __expf(sf[nf][1] - nm0);
            float p10 = __expf(sf[nf][2] - nm1);
            float p11 = __expf(sf[nf][3] - nm1);
            s0 += p00 + p01; s1 += p10 + p11;
            int col = nf * 8 + 2 * qt;
            *(__half2*)(Pp + (mrow + qg) * 72 + col)     = __floats2half2_rn(p00, p01);
            *(__half2*)(Pp + (mrow + qg + 8) * 72 + col) = __floats2half2_rn(p10, p11);
            of[nf][0] *= corr0; of[nf][1] *= corr0;
            of[nf][2] *= corr1; of[nf][3] *= corr1;
        }
        s0 += __shfl_xor_sync(0xffffffffu, s0, 1);
        s0 += __shfl_xor_sync(0xffffffffu, s0, 2);
        s1 += __shfl_xor_sync(0xffffffffu, s1, 1);
        s1 += __shfl_xor_sync(0xffffffffu, s1, 2);
        l0 = l0 * corr0 + s0; l1 = l1 * corr1 + s1;
        m0 = nm0; m1 = nm1;
        __syncwarp();

        // O += P @ V : 4 j-slices x 8 nf, V via ldmatrix.trans
#pragma unroll
        for (int jc = 0; jc < 4; jc++) {
            uint32_t pa[4];
            uint32_t pd = Pb + (uint32_t)((mrow + (mi & 1) * 8 + ri) * AROWB
                                          + jc * 32 + (mi >> 1) * 16);
            ldsm4(pa[0], pa[1], pa[2], pa[3], pd);
#pragma unroll
            for (int np = 0; np < 4; np++) {
                uint32_t vd = Vc + (uint32_t)((jc * 16 + (mi & 1) * 8 + ri) * AROWB
                                              + np * 32 + (mi >> 1) * 16);
                uint32_t r0, r1, r2, r3;
                ldsm4t(r0, r1, r2, r3, vd);
                mma_f16(of[2 * np], pa, r0, r1);
                mma_f16(of[2 * np + 1], pa, r2, r3);
            }
        }
        __syncthreads();
        buf ^= 1;
    }

    const float inv0 = 1.f / l0, inv1 = 1.f / l1;
    const int row0 = qbase + mrow + qg, row1 = row0 + 8;
#pragma unroll
    for (int nf = 0; nf < 8; nf++) {
        int col = nf * 8 + 2 * qt;
        *(__half2*)(g_o + (headbase + row0) * HDIM + col)
            = __floats2half2_rn(of[nf][0] * inv0, of[nf][1] * inv0);
        *(__half2*)(g_o + (headbase + row1) * HDIM + col)
            = __floats2half2_rn(of[nf][2] * inv1, of[nf][3] * inv1);
    }
}

// ---------------------------------------------------------------------------
extern "C" void kernel_launch(void* const* d_in, const int* in_sizes, int n_in,
                              void* d_out, int out_size)
{
    const float* x       = (const float*)d_in[0];
    const float* c       = (const float*)d_in[1];
    const float* Wqkv_x  = (const float*)d_in[2];
    const float* bqkv_x  = (const float*)d_in[3];
    const float* Wqkv_c  = (const float*)d_in[4];
    const float* bqkv_c  = (const float*)d_in[5];
    const float* Wproj_x = (const float*)d_in[6];
    const float* bproj_x = (const float*)d_in[7];
    const float* Wproj_c = (const float*)d_in[8];
    const float* bproj_c = (const float*)d_in[9];
    float* out = (float*)d_out;

    cudaFuncSetAttribute(gemm_h_kernel<0>,
                         cudaFuncAttributeMaxDynamicSharedMemorySize, GEMM_SMEM);
    cudaFuncSetAttribute(gemm_h_kernel<1>,
                         cudaFuncAttributeMaxDynamicSharedMemorySize, GEMM_SMEM);
    cudaFuncSetAttribute(attn_h_kernel,
                         cudaFuncAttributeMaxDynamicSharedMemorySize, ATT_SMEM);

    // resolve device-global scratch addresses (host side)
    __half *hx, *hc, *hWqx, *hWqc, *hWpx, *hWpc;
    cudaGetSymbolAddress((void**)&hx,   g_hx);
    cudaGetSymbolAddress((void**)&hc,   g_hc);
    cudaGetSymbolAddress((void**)&hWqx, g_hWqx);
    cudaGetSymbolAddress((void**)&hWqc, g_hWqc);
    cudaGetSymbolAddress((void**)&hWpx, g_hWpx);
    cudaGetSymbolAddress((void**)&hWpc, g_hWpc);

    // 1) convert inputs + weights to fp16
    const int NX_E  = BB * NXX * DIMX;     // 6291456
    const int NC_E  = BB * NCC * DIMX;     // 786432
    const int WQ_E  = QKVD * DIMX;         // 7077888
    const int WP_E  = DIMX * DIMX;         // 2359296
    f2h_kernel<<<NX_E / 1024, 256>>>(x, hx, NX_E);
    f2h_kernel<<<NC_E / 1024, 256>>>(c, hc, NC_E);
    f2h_kernel<<<WQ_E / 1024, 256>>>(Wqkv_x, hWqx, WQ_E);
    f2h_kernel<<<WQ_E / 1024, 256>>>(Wqkv_c, hWqc, WQ_E);
    f2h_kernel<<<WP_E / 1024, 256>>>(Wproj_x, hWpx, WP_E);
    f2h_kernel<<<WP_E / 1024, 256>>>(Wproj_c, hWpc, WP_E);

    // 2) QKV projections (fp16 GEMM, scatter to g_q/g_k/g_v)
    gemm_h_kernel<0><<<dim3(QKVD / 128, (BB * NXX) / 128), 256, GEMM_SMEM>>>(
        hx, hWqx, bqkv_x, nullptr, NXX, 0);
    gemm_h_kernel<0><<<dim3(QKVD / 128, (BB * NCC) / 128), 256, GEMM_SMEM>>>(
        hc, hWqc, bqkv_c, nullptr, NCC, NXX);

    // 3) joint attention
    attn_h_kernel<<<dim3(NTOTAL / 128, NHEADS, BB), 256, ATT_SMEM>>>();

    // 4) output projections (fp32 out + bias)
    gemm_h_kernel<1><<<dim3(DIMX / 128, (BB * NXX) / 128), 256, GEMM_SMEM>>>(
        nullptr, hWpx, bproj_x, out, NXX, 0);
    gemm_h_kernel<1><<<dim3(DIMX / 128, (BB * NCC) / 128), 256, GEMM_SMEM>>>(
        nullptr, hWpc, bproj_c, out + (size_t)BB * NXX * DIMX, NCC, NXX);
}

// round 13
// speedup vs baseline: 3.0462x; 1.1575x over previous
#include <cuda_runtime.h>
#include <cuda_fp16.h>
#include <cstdint>
#include <math.h>

#define DIMX   1536
#define QKVD   4608
#define NHEADS 24
#define HDIM   64
#define BB     2
#define NXX    2048
#define NCC    256
#define NTOTAL 2304
#define SCALE_LOG2E 0.18033688011112042f   // 0.125 * log2(e)

// ---------------- fp16 scratch (device globals; no allocation) -------------
__device__ __half g_hx[(size_t)BB*NXX*DIMX];
__device__ __half g_hc[(size_t)BB*NCC*DIMX];
__device__ __half g_hWqx[(size_t)QKVD*DIMX];
__device__ __half g_hWqc[(size_t)QKVD*DIMX];
__device__ __half g_hWpx[(size_t)DIMX*DIMX];
__device__ __half g_hWpc[(size_t)DIMX*DIMX];
__device__ __half g_q[(size_t)BB*NHEADS*NTOTAL*HDIM];
__device__ __half g_k[(size_t)BB*NHEADS*NTOTAL*HDIM];
__device__ __half g_v[(size_t)BB*NHEADS*NTOTAL*HDIM];
__device__ __half g_o[(size_t)BB*NHEADS*NTOTAL*HDIM];

// ---------------- helpers ----------------
__device__ __forceinline__ uint32_t s2u(const void* p) {
    return (uint32_t)__cvta_generic_to_shared(p);
}
__device__ __forceinline__ void cp16(uint32_t dst, const void* src) {
    asm volatile("cp.async.cg.shared.global [%0], [%1], 16;" :: "r"(dst), "l"(src));
}
#define CP_COMMIT() asm volatile("cp.async.commit_group;" ::: "memory")
#define CP_WAIT0()  asm volatile("cp.async.wait_group 0;" ::: "memory")
#define CP_WAIT1()  asm volatile("cp.async.wait_group 1;" ::: "memory")
#define CP_WAIT2()  asm volatile("cp.async.wait_group 2;" ::: "memory")

__device__ __forceinline__ float ex2(float x) {
    float r;
    asm("ex2.approx.f32 %0, %1;" : "=f"(r) : "f"(x));
    return r;
}
__device__ __forceinline__ void ldsm4(uint32_t& r0, uint32_t& r1, uint32_t& r2,
                                      uint32_t& r3, uint32_t addr) {
    asm volatile("ldmatrix.sync.aligned.m8n8.x4.shared.b16 {%0,%1,%2,%3}, [%4];"
                 : "=r"(r0), "=r"(r1), "=r"(r2), "=r"(r3) : "r"(addr));
}
__device__ __forceinline__ void ldsm4t(uint32_t& r0, uint32_t& r1, uint32_t& r2,
                                       uint32_t& r3, uint32_t addr) {
    asm volatile("ldmatrix.sync.aligned.m8n8.x4.trans.shared.b16 {%0,%1,%2,%3}, [%4];"
                 : "=r"(r0), "=r"(r1), "=r"(r2), "=r"(r3) : "r"(addr));
}
__device__ __forceinline__ void mma_f16(float* d, const uint32_t* a,
                                        uint32_t b0, uint32_t b1) {
    asm volatile(
        "mma.sync.aligned.m16n8k16.row.col.f32.f16.f16.f32 "
        "{%0,%1,%2,%3}, {%4,%5,%6,%7}, {%8,%9}, {%0,%1,%2,%3};"
        : "+f"(d[0]), "+f"(d[1]), "+f"(d[2]), "+f"(d[3])
        : "r"(a[0]), "r"(a[1]), "r"(a[2]), "r"(a[3]), "r"(b0), "r"(b1));
}

// ---------------- merged fp32 -> fp16 conversion ----------------
// segments in float4 units
#define F4_NX  ((BB*NXX*DIMX) / 4)       // 1572864
#define F4_NC  ((BB*NCC*DIMX) / 4)       // 196608
#define F4_WQ  ((QKVD*DIMX) / 4)         // 1769472
#define F4_WP  ((DIMX*DIMX) / 4)         // 589824
#define F4_TOT (F4_NX + F4_NC + 2*F4_WQ + 2*F4_WP)   // 6488064

__global__ __launch_bounds__(256) void f2h_all_kernel(
    const float* __restrict__ x, const float* __restrict__ c,
    const float* __restrict__ wqx, const float* __restrict__ wqc,
    const float* __restrict__ wpx, const float* __restrict__ wpc)
{
    int i = blockIdx.x * 256 + threadIdx.x;
    if (i >= F4_TOT) return;
    const float* s; __half* d; int off;
    if (i < F4_NX)                          { s = x;   d = g_hx;  off = i; }
    else if (i < F4_NX + F4_NC)             { s = c;   d = g_hc;  off = i - F4_NX; }
    else if (i < F4_NX + F4_NC + F4_WQ)     { s = wqx; d = g_hWqx; off = i - F4_NX - F4_NC; }
    else if (i < F4_NX + F4_NC + 2*F4_WQ)   { s = wqc; d = g_hWqc; off = i - F4_NX - F4_NC - F4_WQ; }
    else if (i < F4_NX + F4_NC + 2*F4_WQ + F4_WP)
                                            { s = wpx; d = g_hWpx; off = i - F4_NX - F4_NC - 2*F4_WQ; }
    else                                    { s = wpc; d = g_hWpc; off = i - F4_NX - F4_NC - 2*F4_WQ - F4_WP; }
    float4 v = *(const float4*)(s + (size_t)off * 4);
    __half2* dp = (__half2*)(d + (size_t)off * 4);
    dp[0] = __floats2half2_rn(v.x, v.y);
    dp[1] = __floats2half2_rn(v.z, v.w);
}

// ======================= fp16 tensor-core GEMM =======================
// Merged x/c sources: blockIdx.y < rowsX -> source 0, else source 1.
// K-tile 32 halves, 4-stage cp.async, fragments via ldmatrix.
// MODE 0: A fp16 row-major, epilogue scatters half2 into g_q/g_k/g_v
// MODE 1: A gathered from g_o [B,H,N,D] fp16, epilogue fp32 +bias to out
#define GK      32
#define GROWB   80                    // bytes per padded row (40 halves)
#define GOP_BYTES (128 * GROWB)       // 10240
#define GSTAGE  (2 * GOP_BYTES)       // 20480
#define GEMM_SMEM (4 * GSTAGE)        // 81920
#define GNITER  (DIMX / GK)           // 48

template<int MODE>
__global__ __launch_bounds__(256, 2) void gemm_h_kernel(
    const __half* __restrict__ A0, const __half* __restrict__ A1,
    const __half* __restrict__ W0, const __half* __restrict__ W1,
    const float* __restrict__ b0, const float* __restrict__ b1,
    float* __restrict__ out, int rowsX)
{
    extern __shared__ char dsm[];
    const uint32_t smem0 = s2u(dsm);
    const int tid = threadIdx.x;
    const int w = tid >> 5, lane = tid & 31;
    const int qg = lane >> 2, qt = lane & 3;
    const int mi = lane >> 3, ri = lane & 7;
    const int mbase = (w & 3) * 32, nbase = (w >> 2) * 64;

    const int by = blockIdx.y;
    const bool isC = (by >= rowsX);
    const __half* A  = isC ? A1 : A0;
    const __half* Wt = isC ? W1 : W0;
    const float* bias = isC ? b1 : b0;
    const int Nt    = isC ? NCC : NXX;
    const int n_off = isC ? NXX : 0;
    const int rowBase = (isC ? (by - rowsX) : by) * 128;
    const int colBase = blockIdx.x * 128;
    float* outf = (MODE == 1) ? (out + (isC ? (size_t)BB * NXX * DIMX : 0)) : out;

    // loader slots: 2 per thread, each one 16B chunk of A and of B
    const __half* asrc[2];
    const __half* wsrc[2];
    uint32_t dsto[2];
    int chh[2];
#pragma unroll
    for (int j = 0; j < 2; j++) {
        int slot = tid + j * 256;          // 0..511
        int r = slot >> 2, ch = slot & 3;  // row, 16B-chunk
        dsto[j] = (uint32_t)(r * GROWB + ch * 16);
        chh[j] = ch;
        wsrc[j] = Wt + (size_t)(colBase + r) * DIMX;
        if (MODE == 0) {
            asrc[j] = A + (size_t)(rowBase + r) * DIMX;
        } else {
            int row = rowBase + r;
            int bi = row / Nt;
            int n = row - bi * Nt;
            asrc[j] = g_o + ((size_t)bi * NHEADS * NTOTAL + n_off + n) * HDIM;
        }
    }

    auto issue = [&](int it) {
        if (it < GNITER) {
            const int k0 = it * GK;
            const uint32_t sa = smem0 + (it & 3) * GSTAGE;
            const uint32_t sb = sa + GOP_BYTES;
#pragma unroll
            for (int j = 0; j < 2; j++) {
                const __half* s;
                if (MODE == 0) {
                    s = asrc[j] + k0 + chh[j] * 8;
                } else {
                    int h = k0 >> 6;
                    int d = (k0 & 63) + chh[j] * 8;
                    s = asrc[j] + (size_t)h * (NTOTAL * HDIM) + d;
                }
                cp16(sa + dsto[j], s);
                cp16(sb + dsto[j], wsrc[j] + k0 + chh[j] * 8);
            }
        }
        CP_COMMIT();   // empty group past the end keeps wait-count uniform
    };

    float acc[2][8][4];
#pragma unroll
    for (int mf = 0; mf < 2; mf++)
#pragma unroll
        for (int nf = 0; nf < 8; nf++)
#pragma unroll
            for (int e = 0; e < 4; e++) acc[mf][nf][e] = 0.f;

    issue(0); issue(1); issue(2);
    for (int it = 0; it < GNITER; it++) {
        CP_WAIT2();
        __syncthreads();
        issue(it + 3);
        const uint32_t sa = smem0 + (it & 3) * GSTAGE;
        const uint32_t sb = sa + GOP_BYTES;
#pragma unroll
        for (int kc = 0; kc < 2; kc++) {
            const int kcb = kc * 32;    // byte offset of 16-half k-slice
            uint32_t a[2][4], b[8][2];
#pragma unroll
            for (int mf = 0; mf < 2; mf++) {
                uint32_t ad = sa + (uint32_t)((mbase + mf * 16 + (mi & 1) * 8 + ri) * GROWB
                                              + kcb + (mi >> 1) * 16);
                ldsm4(a[mf][0], a[mf][1], a[mf][2], a[mf][3], ad);
            }
#pragma unroll
            for (int np = 0; np < 4; np++) {
                uint32_t bd = sb + (uint32_t)((nbase + np * 16 + (mi >> 1) * 8 + ri) * GROWB
                                              + kcb + (mi & 1) * 16);
                uint32_t r0, r1, r2, r3;
                ldsm4(r0, r1, r2, r3, bd);
                b[2 * np][0] = r0; b[2 * np][1] = r1;
                b[2 * np + 1][0] = r2; b[2 * np + 1][1] = r3;
            }
#pragma unroll
            for (int mf = 0; mf < 2; mf++)
#pragma unroll
                for (int nf = 0; nf < 8; nf++)
                    mma_f16(acc[mf][nf], a[mf], b[nf][0], b[nf][1]);
        }
    }

    // epilogue
#pragma unroll
    for (int mf = 0; mf < 2; mf++) {
#pragma unroll
        for (int er = 0; er < 2; er++) {
            int r = rowBase + mbase + mf * 16 + qg + er * 8;
            if (MODE == 0) {
                int bi = r / Nt;
                int n = r - bi * Nt;
#pragma unroll
                for (int nf = 0; nf < 8; nf++) {
                    int cidx = colBase + nbase + nf * 8 + 2 * qt;
                    float v0 = acc[mf][nf][er * 2 + 0] + bias[cidx];
                    float v1 = acc[mf][nf][er * 2 + 1] + bias[cidx + 1];
                    int three = cidx / DIMX;
                    int rem = cidx - three * DIMX;
                    int h = rem >> 6, d = rem & 63;
                    __half* dst = (three == 0) ? g_q : (three == 1) ? g_k : g_v;
                    *(__half2*)(dst + (((size_t)bi * NHEADS + h) * NTOTAL + (n_off + n)) * HDIM + d)
                        = __floats2half2_rn(v0, v1);
                }
            } else {
#pragma unroll
                for (int nf = 0; nf < 8; nf++) {
                    int cidx = colBase + nbase + nf * 8 + 2 * qt;
                    float v0 = acc[mf][nf][er * 2 + 0] + bias[cidx];
                    float v1 = acc[mf][nf][er * 2 + 1] + bias[cidx + 1];
                    *(float2*)(outf + (size_t)r * DIMX + cidx) = make_float2(v0, v1);
                }
            }
        }
    }
}

// ======================= fp16 flash attention =======================
// Br=128 (8 warps x 16 rows), Bc=64, fp16 K/V via cp.async double buffer,
// fragments via ldmatrix (V via ldmatrix.trans). P reuses Q smem.
// Softmax in exp2 domain (scale*log2e folded into S).
#define AROWB 144                     // bytes per padded 64-half row (72 halves)
#define AQ_BYTES  (128 * AROWB)       // 18432
#define AKV_BYTES (64 * AROWB)        // 9216
#define ATT_SMEM (AQ_BYTES + 4 * AKV_BYTES)   // 55296

__global__ __launch_bounds__(256, 2) void attn_h_kernel()
{
    extern __shared__ char dsm[];
    const uint32_t Qb = s2u(dsm);
    uint32_t Kb[2] = { Qb + AQ_BYTES, Qb + AQ_BYTES + AKV_BYTES };
    uint32_t Vb[2] = { Qb + AQ_BYTES + 2 * AKV_BYTES, Qb + AQ_BYTES + 3 * AKV_BYTES };

    const int tid = threadIdx.x;
    const int w = tid >> 5, lane = tid & 31;
    const int qg = lane >> 2, qt = lane & 3;
    const int mi = lane >> 3, ri = lane & 7;
    const int h = blockIdx.y, bi = blockIdx.z;
    const size_t headbase = ((size_t)bi * NHEADS + h) * NTOTAL;
    const int qbase = blockIdx.x * 128;
    const int mrow = w * 16;

    auto issue_tile = [&](int jt, int b) {
#pragma unroll
        for (int i = 0; i < 2; i++) {
            int slot = tid + i * 256;          // 0..511
            int r = slot >> 3, ch = slot & 7;  // row, 16B chunk (8 halves)
            uint32_t off = (uint32_t)(r * AROWB + ch * 16);
            cp16(Kb[b] + off, g_k + (headbase + jt + r) * HDIM + ch * 8);
            cp16(Vb[b] + off, g_v + (headbase + jt + r) * HDIM + ch * 8);
        }
        CP_COMMIT();
    };

    issue_tile(0, 0);

    // stage Q (fp16 direct copy) — 128 rows x 8 chunks (1024 slots)
    {
        __half* Qp = (__half*)dsm;
#pragma unroll
        for (int i = 0; i < 4; i++) {
            int slot = tid + i * 256;           // 0..1023
            int r = slot >> 3, ch = slot & 7;   // row 0..127, chunk 0..7
            uint4 t = *(const uint4*)(g_q + (headbase + qbase + r) * HDIM + ch * 8);
            *(uint4*)(Qp + r * 72 + ch * 8) = t;
        }
    }
    __syncthreads();

    // extract Q fragments: 4 d-slices of 16
    uint32_t qf[4][4];
#pragma unroll
    for (int kf = 0; kf < 4; kf++) {
        uint32_t ad = Qb + (uint32_t)((mrow + (mi & 1) * 8 + ri) * AROWB
                                      + kf * 32 + (mi >> 1) * 16);
        ldsm4(qf[kf][0], qf[kf][1], qf[kf][2], qf[kf][3], ad);
    }
    __syncthreads();
    const uint32_t Pb = Qb;           // P overwrites Q staging
    __half* Pp = (__half*)dsm;

    float of[8][4];
#pragma unroll
    for (int nf = 0; nf < 8; nf++)
#pragma unroll
        for (int e = 0; e < 4; e++) of[nf][e] = 0.f;
    float m0 = -1e30f, m1 = -1e30f, l0 = 0.f, l1 = 0.f;

    int buf = 0;
    for (int jt = 0; jt < NTOTAL; jt += 64) {
        const bool has = (jt + 64) < NTOTAL;
        if (has) issue_tile(jt + 64, buf ^ 1);
        if (has) { CP_WAIT1(); } else { CP_WAIT0(); }
        __syncthreads();

        const uint32_t Kc = Kb[buf];
        const uint32_t Vc = Vb[buf];

        // S = Q K^T : 4 kf x 8 nf
        float sf[8][4];
#pragma unroll
        for (int nf = 0; nf < 8; nf++)
#pragma unroll
            for (int e = 0; e < 4; e++) sf[nf][e] = 0.f;
#pragma unroll
        for (int kf = 0; kf < 4; kf++) {
            const int dcb = kf * 32;
#pragma unroll
            for (int np = 0; np < 4; np++) {
                uint32_t kd = Kc + (uint32_t)((np * 16 + (mi >> 1) * 8 + ri) * AROWB
                                              + dcb + (mi & 1) * 16);
                uint32_t r0, r1, r2, r3;
                ldsm4(r0, r1, r2, r3, kd);
                mma_f16(sf[2 * np], qf[kf], r0, r1);
                mma_f16(sf[2 * np + 1], qf[kf], r2, r3);
            }
        }

        // online softmax in exp2 domain (rows warp-private; quad reduce)
        float mx0 = -1e30f, mx1 = -1e30f;
#pragma unroll
        for (int nf = 0; nf < 8; nf++) {
            sf[nf][0] *= SCALE_LOG2E; sf[nf][1] *= SCALE_LOG2E;
            sf[nf][2] *= SCALE_LOG2E; sf[nf][3] *= SCALE_LOG2E;
            mx0 = fmaxf(mx0, fmaxf(sf[nf][0], sf[nf][1]));
            mx1 = fmaxf(mx1, fmaxf(sf[nf][2], sf[nf][3]));
        }
        mx0 = fmaxf(mx0, __shfl_xor_sync(0xffffffffu, mx0, 1));
        mx0 = fmaxf(mx0, __shfl_xor_sync(0xffffffffu, mx0, 2));
        mx1 = fmaxf(mx1, __shfl_xor_sync(0xffffffffu, mx1, 1));
        mx1 = fmaxf(mx1, __shfl_xor_sync(0xffffffffu, mx1, 2));

        float nm0 = fmaxf(m0, mx0), nm1 = fmaxf(m1, mx1);
        float corr0 = ex2(m0 - nm0), corr1 = ex2(m1 - nm1);
        float s0 = 0.f, s1 = 0.f;
#pragma unroll
        for (int nf = 0; nf < 8; nf++) {
            float p00 = ex2(sf[nf][0] - nm0);
            float p01 = ex2(sf[nf][1] - nm0);
            float p10 = ex2(sf[nf][2] - nm1);
            float p11 = ex2(sf[nf][3] - nm1);
            s0 += p00 + p01; s1 += p10 + p11;
            int col = nf * 8 + 2 * qt;
            *(__half2*)(Pp + (mrow + qg) * 72 + col)     = __floats2half2_rn(p00, p01);
            *(__half2*)(Pp + (mrow + qg + 8) * 72 + col) = __floats2half2_rn(p10, p11);
            of[nf][0] *= corr0; of[nf][1] *= corr0;
            of[nf][2] *= corr1; of[nf][3] *= corr1;
        }
        s0 += __shfl_xor_sync(0xffffffffu, s0, 1);
        s0 += __shfl_xor_sync(0xffffffffu, s0, 2);
        s1 += __shfl_xor_sync(0xffffffffu, s1, 1);
        s1 += __shfl_xor_sync(0xffffffffu, s1, 2);
        l0 = l0 * corr0 + s0; l1 = l1 * corr1 + s1;
        m0 = nm0; m1 = nm1;
        __syncwarp();

        // O += P @ V : 4 j-slices x 8 nf, V via ldmatrix.trans
#pragma unroll
        for (int jc = 0; jc < 4; jc++) {
            uint32_t pa[4];
            uint32_t pd = Pb + (uint32_t)((mrow + (mi & 1) * 8 + ri) * AROWB
                                          + jc * 32 + (mi >> 1) * 16);
            ldsm4(pa[0], pa[1], pa[2], pa[3], pd);
#pragma unroll
            for (int np = 0; np < 4; np++) {
                uint32_t vd = Vc + (uint32_t)((jc * 16 + (mi & 1) * 8 + ri) * AROWB
                                              + np * 32 + (mi >> 1) * 16);
                uint32_t r0, r1, r2, r3;
                ldsm4t(r0, r1, r2, r3, vd);
                mma_f16(of[2 * np], pa, r0, r1);
                mma_f16(of[2 * np + 1], pa, r2, r3);
            }
        }
        __syncthreads();
        buf ^= 1;
    }

    const float inv0 = 1.f / l0, inv1 = 1.f / l1;
    const int row0 = qbase + mrow + qg, row1 = row0 + 8;
#pragma unroll
    for (int nf = 0; nf < 8; nf++) {
        int col = nf * 8 + 2 * qt;
        *(__half2*)(g_o + (headbase + row0) * HDIM + col)
            = __floats2half2_rn(of[nf][0] * inv0, of[nf][1] * inv0);
        *(__half2*)(g_o + (headbase + row1) * HDIM + col)
            = __floats2half2_rn(of[nf][2] * inv1, of[nf][3] * inv1);
    }
}

// ---------------------------------------------------------------------------
extern "C" void kernel_launch(void* const* d_in, const int* in_sizes, int n_in,
                              void* d_out, int out_size)
{
    const float* x       = (const float*)d_in[0];
    const float* c       = (const float*)d_in[1];
    const float* Wqkv_x  = (const float*)d_in[2];
    const float* bqkv_x  = (const float*)d_in[3];
    const float* Wqkv_c  = (const float*)d_in[4];
    const float* bqkv_c  = (const float*)d_in[5];
    const float* Wproj_x = (const float*)d_in[6];
    const float* bproj_x = (const float*)d_in[7];
    const float* Wproj_c = (const float*)d_in[8];
    const float* bproj_c = (const float*)d_in[9];
    float* out = (float*)d_out;

    cudaFuncSetAttribute(gemm_h_kernel<0>,
                         cudaFuncAttributeMaxDynamicSharedMemorySize, GEMM_SMEM);
    cudaFuncSetAttribute(gemm_h_kernel<1>,
                         cudaFuncAttributeMaxDynamicSharedMemorySize, GEMM_SMEM);
    cudaFuncSetAttribute(attn_h_kernel,
                         cudaFuncAttributeMaxDynamicSharedMemorySize, ATT_SMEM);

    __half *hx, *hc, *hWqx, *hWqc, *hWpx, *hWpc;
    cudaGetSymbolAddress((void**)&hx,   g_hx);
    cudaGetSymbolAddress((void**)&hc,   g_hc);
    cudaGetSymbolAddress((void**)&hWqx, g_hWqx);
    cudaGetSymbolAddress((void**)&hWqc, g_hWqc);
    cudaGetSymbolAddress((void**)&hWpx, g_hWpx);
    cudaGetSymbolAddress((void**)&hWpc, g_hWpc);

    // 1) single merged fp32->fp16 conversion
    f2h_all_kernel<<<(F4_TOT + 255) / 256, 256>>>(x, c, Wqkv_x, Wqkv_c, Wproj_x, Wproj_c);

    // 2) merged QKV projection (x rows: 32, c rows: 4)
    gemm_h_kernel<0><<<dim3(QKVD / 128, (BB * NXX) / 128 + (BB * NCC) / 128),
                       256, GEMM_SMEM>>>(
        hx, hc, hWqx, hWqc, bqkv_x, bqkv_c, nullptr, (BB * NXX) / 128);

    // 3) joint attention
    attn_h_kernel<<<dim3(NTOTAL / 128, NHEADS, BB), 256, ATT_SMEM>>>();

    // 4) merged output projection
    gemm_h_kernel<1><<<dim3(DIMX / 128, (BB * NXX) / 128 + (BB * NCC) / 128),
                       256, GEMM_SMEM>>>(
        nullptr, nullptr, hWpx, hWpc, bproj_x, bproj_c, out, (BB * NXX) / 128);
}

// round 14
// speedup vs baseline: 3.1166x; 1.0231x over previous
#include <cuda_runtime.h>
#include <cuda_fp16.h>
#include <cstdint>
#include <math.h>

#define DIMX   1536
#define QKVD   4608
#define NHEADS 24
#define HDIM   64
#define BB     2
#define NXX    2048
#define NCC    256
#define NTOTAL 2304
#define SCALE_LOG2E 0.18033688011112042f   // 0.125 * log2(e)

// ---------------- fp16 scratch (device globals; no allocation) -------------
__device__ __half g_hx[(size_t)BB*NXX*DIMX];
__device__ __half g_hc[(size_t)BB*NCC*DIMX];
__device__ __half g_hWqx[(size_t)QKVD*DIMX];
__device__ __half g_hWqc[(size_t)QKVD*DIMX];
__device__ __half g_hWpx[(size_t)DIMX*DIMX];
__device__ __half g_hWpc[(size_t)DIMX*DIMX];
__device__ __half g_q[(size_t)BB*NHEADS*NTOTAL*HDIM];
__device__ __half g_k[(size_t)BB*NHEADS*NTOTAL*HDIM];
__device__ __half g_v[(size_t)BB*NHEADS*NTOTAL*HDIM];
__device__ __half g_o[(size_t)BB*NHEADS*NTOTAL*HDIM];

// ---------------- helpers ----------------
__device__ __forceinline__ uint32_t s2u(const void* p) {
    return (uint32_t)__cvta_generic_to_shared(p);
}
__device__ __forceinline__ void cp16(uint32_t dst, const void* src) {
    asm volatile("cp.async.cg.shared.global [%0], [%1], 16;" :: "r"(dst), "l"(src));
}
#define CP_COMMIT() asm volatile("cp.async.commit_group;" ::: "memory")
#define CP_WAIT0()  asm volatile("cp.async.wait_group 0;" ::: "memory")
#define CP_WAIT1()  asm volatile("cp.async.wait_group 1;" ::: "memory")
#define CP_WAIT2()  asm volatile("cp.async.wait_group 2;" ::: "memory")

__device__ __forceinline__ float ex2(float x) {
    float r;
    asm("ex2.approx.f32 %0, %1;" : "=f"(r) : "f"(x));
    return r;
}
__device__ __forceinline__ void ldsm4(uint32_t& r0, uint32_t& r1, uint32_t& r2,
                                      uint32_t& r3, uint32_t addr) {
    asm volatile("ldmatrix.sync.aligned.m8n8.x4.shared.b16 {%0,%1,%2,%3}, [%4];"
                 : "=r"(r0), "=r"(r1), "=r"(r2), "=r"(r3) : "r"(addr));
}
__device__ __forceinline__ void ldsm4t(uint32_t& r0, uint32_t& r1, uint32_t& r2,
                                       uint32_t& r3, uint32_t addr) {
    asm volatile("ldmatrix.sync.aligned.m8n8.x4.trans.shared.b16 {%0,%1,%2,%3}, [%4];"
                 : "=r"(r0), "=r"(r1), "=r"(r2), "=r"(r3) : "r"(addr));
}
__device__ __forceinline__ void mma_f16(float* d, const uint32_t* a,
                                        uint32_t b0, uint32_t b1) {
    asm volatile(
        "mma.sync.aligned.m16n8k16.row.col.f32.f16.f16.f32 "
        "{%0,%1,%2,%3}, {%4,%5,%6,%7}, {%8,%9}, {%0,%1,%2,%3};"
        : "+f"(d[0]), "+f"(d[1]), "+f"(d[2]), "+f"(d[3])
        : "r"(a[0]), "r"(a[1]), "r"(a[2]), "r"(a[3]), "r"(b0), "r"(b1));
}

// ---------------- merged fp32 -> fp16 conversion ----------------
#define F4_NX  ((BB*NXX*DIMX) / 4)
#define F4_NC  ((BB*NCC*DIMX) / 4)
#define F4_WQ  ((QKVD*DIMX) / 4)
#define F4_WP  ((DIMX*DIMX) / 4)
#define F4_TOT (F4_NX + F4_NC + 2*F4_WQ + 2*F4_WP)

__global__ __launch_bounds__(256) void f2h_all_kernel(
    const float* __restrict__ x, const float* __restrict__ c,
    const float* __restrict__ wqx, const float* __restrict__ wqc,
    const float* __restrict__ wpx, const float* __restrict__ wpc)
{
    int i = blockIdx.x * 256 + threadIdx.x;
    if (i >= F4_TOT) return;
    const float* s; __half* d; int off;
    if (i < F4_NX)                          { s = x;   d = g_hx;  off = i; }
    else if (i < F4_NX + F4_NC)             { s = c;   d = g_hc;  off = i - F4_NX; }
    else if (i < F4_NX + F4_NC + F4_WQ)     { s = wqx; d = g_hWqx; off = i - F4_NX - F4_NC; }
    else if (i < F4_NX + F4_NC + 2*F4_WQ)   { s = wqc; d = g_hWqc; off = i - F4_NX - F4_NC - F4_WQ; }
    else if (i < F4_NX + F4_NC + 2*F4_WQ + F4_WP)
                                            { s = wpx; d = g_hWpx; off = i - F4_NX - F4_NC - 2*F4_WQ; }
    else                                    { s = wpc; d = g_hWpc; off = i - F4_NX - F4_NC - 2*F4_WQ - F4_WP; }
    float4 v = *(const float4*)(s + (size_t)off * 4);
    __half2* dp = (__half2*)(d + (size_t)off * 4);
    dp[0] = __floats2half2_rn(v.x, v.y);
    dp[1] = __floats2half2_rn(v.z, v.w);
}

// ======================= fp16 tensor-core GEMM (unchanged) =======================
#define GK      32
#define GROWB   80
#define GOP_BYTES (128 * GROWB)
#define GSTAGE  (2 * GOP_BYTES)
#define GEMM_SMEM (4 * GSTAGE)
#define GNITER  (DIMX / GK)

template<int MODE>
__global__ __launch_bounds__(256, 2) void gemm_h_kernel(
    const __half* __restrict__ A0, const __half* __restrict__ A1,
    const __half* __restrict__ W0, const __half* __restrict__ W1,
    const float* __restrict__ b0, const float* __restrict__ b1,
    float* __restrict__ out, int rowsX)
{
    extern __shared__ char dsm[];
    const uint32_t smem0 = s2u(dsm);
    const int tid = threadIdx.x;
    const int w = tid >> 5, lane = tid & 31;
    const int qg = lane >> 2, qt = lane & 3;
    const int mi = lane >> 3, ri = lane & 7;
    const int mbase = (w & 3) * 32, nbase = (w >> 2) * 64;

    const int by = blockIdx.y;
    const bool isC = (by >= rowsX);
    const __half* A  = isC ? A1 : A0;
    const __half* Wt = isC ? W1 : W0;
    const float* bias = isC ? b1 : b0;
    const int Nt    = isC ? NCC : NXX;
    const int n_off = isC ? NXX : 0;
    const int rowBase = (isC ? (by - rowsX) : by) * 128;
    const int colBase = blockIdx.x * 128;
    float* outf = (MODE == 1) ? (out + (isC ? (size_t)BB * NXX * DIMX : 0)) : out;

    const __half* asrc[2];
    const __half* wsrc[2];
    uint32_t dsto[2];
    int chh[2];
#pragma unroll
    for (int j = 0; j < 2; j++) {
        int slot = tid + j * 256;
        int r = slot >> 2, ch = slot & 3;
        dsto[j] = (uint32_t)(r * GROWB + ch * 16);
        chh[j] = ch;
        wsrc[j] = Wt + (size_t)(colBase + r) * DIMX;
        if (MODE == 0) {
            asrc[j] = A + (size_t)(rowBase + r) * DIMX;
        } else {
            int row = rowBase + r;
            int bi = row / Nt;
            int n = row - bi * Nt;
            asrc[j] = g_o + ((size_t)bi * NHEADS * NTOTAL + n_off + n) * HDIM;
        }
    }

    auto issue = [&](int it) {
        if (it < GNITER) {
            const int k0 = it * GK;
            const uint32_t sa = smem0 + (it & 3) * GSTAGE;
            const uint32_t sb = sa + GOP_BYTES;
#pragma unroll
            for (int j = 0; j < 2; j++) {
                const __half* s;
                if (MODE == 0) {
                    s = asrc[j] + k0 + chh[j] * 8;
                } else {
                    int h = k0 >> 6;
                    int d = (k0 & 63) + chh[j] * 8;
                    s = asrc[j] + (size_t)h * (NTOTAL * HDIM) + d;
                }
                cp16(sa + dsto[j], s);
                cp16(sb + dsto[j], wsrc[j] + k0 + chh[j] * 8);
            }
        }
        CP_COMMIT();
    };

    float acc[2][8][4];
#pragma unroll
    for (int mf = 0; mf < 2; mf++)
#pragma unroll
        for (int nf = 0; nf < 8; nf++)
#pragma unroll
            for (int e = 0; e < 4; e++) acc[mf][nf][e] = 0.f;

    issue(0); issue(1); issue(2);
    for (int it = 0; it < GNITER; it++) {
        CP_WAIT2();
        __syncthreads();
        issue(it + 3);
        const uint32_t sa = smem0 + (it & 3) * GSTAGE;
        const uint32_t sb = sa + GOP_BYTES;
#pragma unroll
        for (int kc = 0; kc < 2; kc++) {
            const int kcb = kc * 32;
            uint32_t a[2][4], b[8][2];
#pragma unroll
            for (int mf = 0; mf < 2; mf++) {
                uint32_t ad = sa + (uint32_t)((mbase + mf * 16 + (mi & 1) * 8 + ri) * GROWB
                                              + kcb + (mi >> 1) * 16);
                ldsm4(a[mf][0], a[mf][1], a[mf][2], a[mf][3], ad);
            }
#pragma unroll
            for (int np = 0; np < 4; np++) {
                uint32_t bd = sb + (uint32_t)((nbase + np * 16 + (mi >> 1) * 8 + ri) * GROWB
                                              + kcb + (mi & 1) * 16);
                uint32_t r0, r1, r2, r3;
                ldsm4(r0, r1, r2, r3, bd);
                b[2 * np][0] = r0; b[2 * np][1] = r1;
                b[2 * np + 1][0] = r2; b[2 * np + 1][1] = r3;
            }
#pragma unroll
            for (int mf = 0; mf < 2; mf++)
#pragma unroll
                for (int nf = 0; nf < 8; nf++)
                    mma_f16(acc[mf][nf], a[mf], b[nf][0], b[nf][1]);
        }
    }

#pragma unroll
    for (int mf = 0; mf < 2; mf++) {
#pragma unroll
        for (int er = 0; er < 2; er++) {
            int r = rowBase + mbase + mf * 16 + qg + er * 8;
            if (MODE == 0) {
                int bi = r / Nt;
                int n = r - bi * Nt;
#pragma unroll
                for (int nf = 0; nf < 8; nf++) {
                    int cidx = colBase + nbase + nf * 8 + 2 * qt;
                    float v0 = acc[mf][nf][er * 2 + 0] + bias[cidx];
                    float v1 = acc[mf][nf][er * 2 + 1] + bias[cidx + 1];
                    int three = cidx / DIMX;
                    int rem = cidx - three * DIMX;
                    int h = rem >> 6, d = rem & 63;
                    __half* dst = (three == 0) ? g_q : (three == 1) ? g_k : g_v;
                    *(__half2*)(dst + (((size_t)bi * NHEADS + h) * NTOTAL + (n_off + n)) * HDIM + d)
                        = __floats2half2_rn(v0, v1);
                }
            } else {
#pragma unroll
                for (int nf = 0; nf < 8; nf++) {
                    int cidx = colBase + nbase + nf * 8 + 2 * qt;
                    float v0 = acc[mf][nf][er * 2 + 0] + bias[cidx];
                    float v1 = acc[mf][nf][er * 2 + 1] + bias[cidx + 1];
                    *(float2*)(outf + (size_t)r * DIMX + cidx) = make_float2(v0, v1);
                }
            }
        }
    }
}

// ======================= fp16 flash attention =======================
// Br=128 (8 warps x 16 rows), Bc=64. P stays in registers: the S C-fragment
// layout equals the PV A-fragment layout, so exp(S) packs directly into
// A-frag half2 regs (no smem round trip). exp via ex2.approx.f16x2.
#define AROWB 144                     // bytes per padded 64-half row
#define AQ_BYTES  (128 * AROWB)
#define AKV_BYTES (64 * AROWB)
#define ATT_SMEM (AQ_BYTES + 4 * AKV_BYTES)

__global__ __launch_bounds__(256, 2) void attn_h_kernel()
{
    extern __shared__ char dsm[];
    const uint32_t Qb = s2u(dsm);
    uint32_t Kb[2] = { Qb + AQ_BYTES, Qb + AQ_BYTES + AKV_BYTES };
    uint32_t Vb[2] = { Qb + AQ_BYTES + 2 * AKV_BYTES, Qb + AQ_BYTES + 3 * AKV_BYTES };

    const int tid = threadIdx.x;
    const int w = tid >> 5, lane = tid & 31;
    const int qg = lane >> 2, qt = lane & 3;
    const int mi = lane >> 3, ri = lane & 7;
    const int h = blockIdx.y, bi = blockIdx.z;
    const size_t headbase = ((size_t)bi * NHEADS + h) * NTOTAL;
    const int qbase = blockIdx.x * 128;
    const int mrow = w * 16;

    auto issue_tile = [&](int jt, int b) {
#pragma unroll
        for (int i = 0; i < 2; i++) {
            int slot = tid + i * 256;
            int r = slot >> 3, ch = slot & 7;
            uint32_t off = (uint32_t)(r * AROWB + ch * 16);
            cp16(Kb[b] + off, g_k + (headbase + jt + r) * HDIM + ch * 8);
            cp16(Vb[b] + off, g_v + (headbase + jt + r) * HDIM + ch * 8);
        }
        CP_COMMIT();
    };

    issue_tile(0, 0);

    // stage Q (fp16): 128 rows x 8 chunks
    {
        __half* Qp = (__half*)dsm;
#pragma unroll
        for (int i = 0; i < 4; i++) {
            int slot = tid + i * 256;
            int r = slot >> 3, ch = slot & 7;
            uint4 t = *(const uint4*)(g_q + (headbase + qbase + r) * HDIM + ch * 8);
            *(uint4*)(Qp + r * 72 + ch * 8) = t;
        }
    }
    __syncthreads();

    uint32_t qf[4][4];
#pragma unroll
    for (int kf = 0; kf < 4; kf++) {
        uint32_t ad = Qb + (uint32_t)((mrow + (mi & 1) * 8 + ri) * AROWB
                                      + kf * 32 + (mi >> 1) * 16);
        ldsm4(qf[kf][0], qf[kf][1], qf[kf][2], qf[kf][3], ad);
    }

    float of[8][4];
#pragma unroll
    for (int nf = 0; nf < 8; nf++)
#pragma unroll
        for (int e = 0; e < 4; e++) of[nf][e] = 0.f;
    float m0 = -1e30f, m1 = -1e30f, l0 = 0.f, l1 = 0.f;

    int buf = 0;
    for (int jt = 0; jt < NTOTAL; jt += 64) {
        const bool has = (jt + 64) < NTOTAL;
        if (has) issue_tile(jt + 64, buf ^ 1);
        if (has) { CP_WAIT1(); } else { CP_WAIT0(); }
        __syncthreads();

        const uint32_t Kc = Kb[buf];
        const uint32_t Vc = Vb[buf];

        // S = Q K^T
        float sf[8][4];
#pragma unroll
        for (int nf = 0; nf < 8; nf++)
#pragma unroll
            for (int e = 0; e < 4; e++) sf[nf][e] = 0.f;
#pragma unroll
        for (int kf = 0; kf < 4; kf++) {
            const int dcb = kf * 32;
#pragma unroll
            for (int np = 0; np < 4; np++) {
                uint32_t kd = Kc + (uint32_t)((np * 16 + (mi >> 1) * 8 + ri) * AROWB
                                              + dcb + (mi & 1) * 16);
                uint32_t r0, r1, r2, r3;
                ldsm4(r0, r1, r2, r3, kd);
                mma_f16(sf[2 * np], qf[kf], r0, r1);
                mma_f16(sf[2 * np + 1], qf[kf], r2, r3);
            }
        }

        // online softmax in exp2 domain; P packed directly into A-frag regs
        float mx0 = -1e30f, mx1 = -1e30f;
#pragma unroll
        for (int nf = 0; nf < 8; nf++) {
            sf[nf][0] *= SCALE_LOG2E; sf[nf][1] *= SCALE_LOG2E;
            sf[nf][2] *= SCALE_LOG2E; sf[nf][3] *= SCALE_LOG2E;
            mx0 = fmaxf(mx0, fmaxf(sf[nf][0], sf[nf][1]));
            mx1 = fmaxf(mx1, fmaxf(sf[nf][2], sf[nf][3]));
        }
        mx0 = fmaxf(mx0, __shfl_xor_sync(0xffffffffu, mx0, 1));
        mx0 = fmaxf(mx0, __shfl_xor_sync(0xffffffffu, mx0, 2));
        mx1 = fmaxf(mx1, __shfl_xor_sync(0xffffffffu, mx1, 1));
        mx1 = fmaxf(mx1, __shfl_xor_sync(0xffffffffu, mx1, 2));

        float nm0 = fmaxf(m0, mx0), nm1 = fmaxf(m1, mx1);
        float corr0 = ex2(m0 - nm0), corr1 = ex2(m1 - nm1);
        float s0 = 0.f, s1 = 0.f;
        uint32_t pfrag[4][4];
#pragma unroll
        for (int nf = 0; nf < 8; nf++) {
            __half2 e01 = h2exp2(__floats2half2_rn(sf[nf][0] - nm0, sf[nf][1] - nm0));
            __half2 e23 = h2exp2(__floats2half2_rn(sf[nf][2] - nm1, sf[nf][3] - nm1));
            float2 f01 = __half22float2(e01);
            float2 f23 = __half22float2(e23);
            s0 += f01.x + f01.y;
            s1 += f23.x + f23.y;
            pfrag[nf >> 1][((nf & 1) << 1) + 0] = *reinterpret_cast<uint32_t*>(&e01);
            pfrag[nf >> 1][((nf & 1) << 1) + 1] = *reinterpret_cast<uint32_t*>(&e23);
            of[nf][0] *= corr0; of[nf][1] *= corr0;
            of[nf][2] *= corr1; of[nf][3] *= corr1;
        }
        s0 += __shfl_xor_sync(0xffffffffu, s0, 1);
        s0 += __shfl_xor_sync(0xffffffffu, s0, 2);
        s1 += __shfl_xor_sync(0xffffffffu, s1, 1);
        s1 += __shfl_xor_sync(0xffffffffu, s1, 2);
        l0 = l0 * corr0 + s0; l1 = l1 * corr1 + s1;
        m0 = nm0; m1 = nm1;

        // O += P @ V : V via ldmatrix.trans; P already in A-frag registers
#pragma unroll
        for (int jc = 0; jc < 4; jc++) {
#pragma unroll
            for (int np = 0; np < 4; np++) {
                uint32_t vd = Vc + (uint32_t)((jc * 16 + (mi & 1) * 8 + ri) * AROWB
                                              + np * 32 + (mi >> 1) * 16);
                uint32_t r0, r1, r2, r3;
                ldsm4t(r0, r1, r2, r3, vd);
                mma_f16(of[2 * np], pfrag[jc], r0, r1);
                mma_f16(of[2 * np + 1], pfrag[jc], r2, r3);
            }
        }
        __syncthreads();
        buf ^= 1;
    }

    const float inv0 = 1.f / l0, inv1 = 1.f / l1;
    const int row0 = qbase + mrow + qg, row1 = row0 + 8;
#pragma unroll
    for (int nf = 0; nf < 8; nf++) {
        int col = nf * 8 + 2 * qt;
        *(__half2*)(g_o + (headbase + row0) * HDIM + col)
            = __floats2half2_rn(of[nf][0] * inv0, of[nf][1] * inv0);
        *(__half2*)(g_o + (headbase + row1) * HDIM + col)
            = __floats2half2_rn(of[nf][2] * inv1, of[nf][3] * inv1);
    }
}

// ---------------------------------------------------------------------------
extern "C" void kernel_launch(void* const* d_in, const int* in_sizes, int n_in,
                              void* d_out, int out_size)
{
    const float* x       = (const float*)d_in[0];
    const float* c       = (const float*)d_in[1];
    const float* Wqkv_x  = (const float*)d_in[2];
    const float* bqkv_x  = (const float*)d_in[3];
    const float* Wqkv_c  = (const float*)d_in[4];
    const float* bqkv_c  = (const float*)d_in[5];
    const float* Wproj_x = (const float*)d_in[6];
    const float* bproj_x = (const float*)d_in[7];
    const float* Wproj_c = (const float*)d_in[8];
    const float* bproj_c = (const float*)d_in[9];
    float* out = (float*)d_out;

    cudaFuncSetAttribute(gemm_h_kernel<0>,
                         cudaFuncAttributeMaxDynamicSharedMemorySize, GEMM_SMEM);
    cudaFuncSetAttribute(gemm_h_kernel<1>,
                         cudaFuncAttributeMaxDynamicSharedMemorySize, GEMM_SMEM);
    cudaFuncSetAttribute(attn_h_kernel,
                         cudaFuncAttributeMaxDynamicSharedMemorySize, ATT_SMEM);

    __half *hx, *hc, *hWqx, *hWqc, *hWpx, *hWpc;
    cudaGetSymbolAddress((void**)&hx,   g_hx);
    cudaGetSymbolAddress((void**)&hc,   g_hc);
    cudaGetSymbolAddress((void**)&hWqx, g_hWqx);
    cudaGetSymbolAddress((void**)&hWqc, g_hWqc);
    cudaGetSymbolAddress((void**)&hWpx, g_hWpx);
    cudaGetSymbolAddress((void**)&hWpc, g_hWpc);

    f2h_all_kernel<<<(F4_TOT + 255) / 256, 256>>>(x, c, Wqkv_x, Wqkv_c, Wproj_x, Wproj_c);

    gemm_h_kernel<0><<<dim3(QKVD / 128, (BB * NXX) / 128 + (BB * NCC) / 128),
                       256, GEMM_SMEM>>>(
        hx, hc, hWqx, hWqc, bqkv_x, bqkv_c, nullptr, (BB * NXX) / 128);

    attn_h_kernel<<<dim3(NTOTAL / 128, NHEADS, BB), 256, ATT_SMEM>>>();

    gemm_h_kernel<1><<<dim3(DIMX / 128, (BB * NXX) / 128 + (BB * NCC) / 128),
                       256, GEMM_SMEM>>>(
        nullptr, nullptr, hWpx, hWpc, bproj_x, bproj_c, out, (BB * NXX) / 128);
}